// round 2
// baseline (speedup 1.0000x reference)
#include <cuda_runtime.h>
#include <cuda_bf16.h>
#include <cstdint>

// Problem constants
#define S_LEN 512
#define BATCH 64
#define D_IN  512
#define H_DIM 1024
#define G4    4096            // 4*H
#define M_ROWS (S_LEN * BATCH)   // 32768

// ---------------- device scratch (no allocations allowed) ----------------
__device__ float g_Wx_p[D_IN * G4];            // 8 MB   permuted Wx
__device__ float g_Wh_p[H_DIM * G4];           // 16 MB  permuted Wh
__device__ float g_bh_p[G4];                   // 16 KB  permuted bias
__device__ float g_gx[(size_t)M_ROWS * G4];    // 512 MB gx = x @ Wx (permuted cols)
__device__ float g_hbuf[2][BATCH * H_DIM];     // ping-pong h
__device__ unsigned g_bar_count;
__device__ unsigned g_bar_gen;

// ---------------- column permutation: new_col = hc*4 + g, old_col = g*1024 + hc ----
__global__ void permute_w(const float* __restrict__ Wx,
                          const float* __restrict__ Wh,
                          const float* __restrict__ bh) {
    int total = (D_IN + H_DIM + 1) * G4;
    for (int i = blockIdx.x * blockDim.x + threadIdx.x; i < total;
         i += gridDim.x * blockDim.x) {
        int r  = i >> 12;        // stacked row: [0,512) Wx, [512,1536) Wh, 1536 bias
        int cn = i & 4095;       // new column
        int hc = cn >> 2;
        int g  = cn & 3;
        int co = g * H_DIM + hc; // old column
        if (r < D_IN) {
            g_Wx_p[r * G4 + cn] = Wx[r * G4 + co];
        } else if (r < D_IN + H_DIM) {
            int k = r - D_IN;
            g_Wh_p[k * G4 + cn] = Wh[k * G4 + co];
        } else {
            g_bh_p[cn] = bh[co];
        }
    }
}

// ---------------- GEMM: g_gx[M_ROWS x 4096] = x[M_ROWS x 512] @ g_Wx_p[512 x 4096]
// 128x128 tile, BK=8, 256 threads, 8x8 microtile per thread.
__global__ __launch_bounds__(256) void gemm_gx(const float* __restrict__ A) {
    __shared__ float As[8][128];   // transposed A tile: As[k][m]
    __shared__ float Bs[8][128];

    const int m0 = blockIdx.y * 128;
    const int n0 = blockIdx.x * 128;
    const int t  = threadIdx.x;
    const int ty = t >> 4;         // 0..15 -> 8 rows each
    const int tx = t & 15;         // 0..15 -> 8 cols each

    const int arow = t >> 1, ak4 = (t & 1) * 4;
    const int brow = t >> 5, bc4 = (t & 31) * 4;

    float acc[8][8];
#pragma unroll
    for (int i = 0; i < 8; ++i)
#pragma unroll
        for (int j = 0; j < 8; ++j) acc[i][j] = 0.f;

    for (int k0 = 0; k0 < D_IN; k0 += 8) {
        float4 av = *(const float4*)&A[(size_t)(m0 + arow) * D_IN + k0 + ak4];
        float4 bv = *(const float4*)&g_Wx_p[(size_t)(k0 + brow) * G4 + n0 + bc4];
        As[ak4 + 0][arow] = av.x;
        As[ak4 + 1][arow] = av.y;
        As[ak4 + 2][arow] = av.z;
        As[ak4 + 3][arow] = av.w;
        *(float4*)&Bs[brow][bc4] = bv;
        __syncthreads();
#pragma unroll
        for (int k = 0; k < 8; ++k) {
            float a[8], b[8];
            *(float4*)(a)     = *(const float4*)&As[k][ty * 8];
            *(float4*)(a + 4) = *(const float4*)&As[k][ty * 8 + 4];
            *(float4*)(b)     = *(const float4*)&Bs[k][tx * 8];
            *(float4*)(b + 4) = *(const float4*)&Bs[k][tx * 8 + 4];
#pragma unroll
            for (int i = 0; i < 8; ++i)
#pragma unroll
                for (int j = 0; j < 8; ++j) acc[i][j] = fmaf(a[i], b[j], acc[i][j]);
        }
        __syncthreads();
    }
#pragma unroll
    for (int i = 0; i < 8; ++i) {
        size_t r = (size_t)(m0 + ty * 8 + i) * G4 + n0 + tx * 8;
        *(float4*)&g_gx[r]     = make_float4(acc[i][0], acc[i][1], acc[i][2], acc[i][3]);
        *(float4*)&g_gx[r + 4] = make_float4(acc[i][4], acc[i][5], acc[i][6], acc[i][7]);
    }
}

// ---------------- software grid barrier (all 128 CTAs co-resident) ----------------
__device__ __forceinline__ void grid_sync(unsigned& bar) {
    __syncthreads();
    if (threadIdx.x == 0) {
        __threadfence();
        unsigned t = atomicAdd(&g_bar_count, 1u);
        bar += 1;
        if (t == gridDim.x - 1u) {
            atomicExch(&g_bar_count, 0u);
            __threadfence();
            atomicAdd(&g_bar_gen, 1u);
        } else {
            while ((int)(atomicAdd(&g_bar_gen, 0u) - bar) < 0) __nanosleep(64);
        }
    }
    __syncthreads();
}

__device__ __forceinline__ float sigm(float x) {
    return 1.0f / (1.0f + __expf(-x));
}

// ---------------- persistent recurrence kernel ----------------
// 128 blocks x 256 threads. Block owns 8 h-columns = 32 contiguous permuted gate
// columns. Per step: gates(64x32) = h(64x1024) @ Wh_p(1024, 32cols) + gx_t + b,
// then LSTM elementwise for the owned (b, hc) pairs; c stays in SMEM all kernel.
__global__ __launch_bounds__(256) void lstm_rec(const float* __restrict__ h0,
                                                const float* __restrict__ c0,
                                                float* __restrict__ out) {
    __shared__ float h_s[64 * 65];      // chunk of h, transposed: h_s[k*65 + b]
    __shared__ float Ws[64 * 32];       // Wh chunk: Ws[k*32 + c]
    __shared__ float gates_s[64 * 32];  // gates tile
    __shared__ float c_s[64 * 8];       // persistent cell state tile

    const int tid = threadIdx.x;
    const int bid = blockIdx.x;
    const int row = tid & 63;   // batch row this thread computes
    const int cg  = tid >> 6;   // column group (8 cols each)
    const int cb  = bid * 32;   // permuted gate-column base
    const int hcb = bid * 8;    // h-column base

    // bias registers (constant across steps)
    float breg[8];
#pragma unroll
    for (int j = 0; j < 8; ++j) breg[j] = g_bh_p[cb + cg * 8 + j];

    // init c tile and our slice of h buffer 0
    for (int p = tid; p < 512; p += 256) {
        int b = p >> 3, hl = p & 7;
        c_s[b * 8 + hl] = c0[b * H_DIM + hcb + hl];
        g_hbuf[0][b * H_DIM + hcb + hl] = h0[b * H_DIM + hcb + hl];
    }

    unsigned bar = 0;
    if (tid == 0) bar = atomicAdd(&g_bar_gen, 0u);  // entry generation (monotonic across replays)
    grid_sync(bar);

    for (int t = 0; t < S_LEN; ++t) {
        const int cur = t & 1;
        const float* hsrc = g_hbuf[cur];
        float acc[8];
#pragma unroll
        for (int j = 0; j < 8; ++j) acc[j] = 0.f;

        for (int kc = 0; kc < 16; ++kc) {
            __syncthreads();
            // load h chunk (64 k x 64 b), transpose into smem; L2 reads (cross-block data)
#pragma unroll
            for (int q = 0; q < 4; ++q) {
                int s  = tid + 256 * q;
                int b  = s >> 4;
                int ko = (s & 15) * 4;
                float4 v = __ldcg((const float4*)(hsrc + b * H_DIM + kc * 64 + ko));
                h_s[(ko + 0) * 65 + b] = v.x;
                h_s[(ko + 1) * 65 + b] = v.y;
                h_s[(ko + 2) * 65 + b] = v.z;
                h_s[(ko + 3) * 65 + b] = v.w;
            }
            // load Wh chunk (64 k x 32 cols)
#pragma unroll
            for (int q = 0; q < 2; ++q) {
                int s  = tid + 256 * q;
                int r  = s >> 3;
                int c4 = (s & 7) * 4;
                *(float4*)&Ws[r * 32 + c4] =
                    *(const float4*)&g_Wh_p[(size_t)(kc * 64 + r) * G4 + cb + c4];
            }
            __syncthreads();
#pragma unroll 16
            for (int kk = 0; kk < 64; ++kk) {
                float  hv = h_s[kk * 65 + row];
                float4 w0 = *(const float4*)&Ws[kk * 32 + cg * 8];
                float4 w1 = *(const float4*)&Ws[kk * 32 + cg * 8 + 4];
                acc[0] = fmaf(hv, w0.x, acc[0]);
                acc[1] = fmaf(hv, w0.y, acc[1]);
                acc[2] = fmaf(hv, w0.z, acc[2]);
                acc[3] = fmaf(hv, w0.w, acc[3]);
                acc[4] = fmaf(hv, w1.x, acc[4]);
                acc[5] = fmaf(hv, w1.y, acc[5]);
                acc[6] = fmaf(hv, w1.z, acc[6]);
                acc[7] = fmaf(hv, w1.w, acc[7]);
            }
        }

        // add gx_t + bias, stage gates in smem
        {
            size_t gxoff = (size_t)(t * BATCH + row) * G4 + cb + cg * 8;
            float4 g0 = *(const float4*)&g_gx[gxoff];
            float4 g1 = *(const float4*)&g_gx[gxoff + 4];
            float* gs = &gates_s[row * 32 + cg * 8];
            gs[0] = acc[0] + g0.x + breg[0];
            gs[1] = acc[1] + g0.y + breg[1];
            gs[2] = acc[2] + g0.z + breg[2];
            gs[3] = acc[3] + g0.w + breg[3];
            gs[4] = acc[4] + g1.x + breg[4];
            gs[5] = acc[5] + g1.y + breg[5];
            gs[6] = acc[6] + g1.z + breg[6];
            gs[7] = acc[7] + g1.w + breg[7];
        }
        __syncthreads();

        // elementwise LSTM update for owned (b, hc) pairs
        float* hdst = g_hbuf[cur ^ 1];
#pragma unroll
        for (int q = 0; q < 2; ++q) {
            int p  = tid + 256 * q;
            int b  = p >> 3;
            int hl = p & 7;
            const float* gs = &gates_s[b * 32 + hl * 4];
            float gi = gs[0], gf = gs[1], gj = gs[2], go = gs[3];
            float fg = sigm(gf + 1.0f);   // FORGET_BIAS = 1.0
            float ig = sigm(gi);
            float og = sigm(go);
            float cnew = c_s[b * 8 + hl] * fg + ig * tanhf(gj);
            c_s[b * 8 + hl] = cnew;
            float hnew = tanhf(cnew) * og;
            hdst[b * H_DIM + hcb + hl] = hnew;
            if (t == S_LEN - 1) {
                out[b * H_DIM + hcb + hl] = hnew;                      // h
                out[BATCH * H_DIM + b * H_DIM + hcb + hl] = cnew;      // c
            }
        }
        grid_sync(bar);
    }
}

// ---------------- launch ----------------
extern "C" void kernel_launch(void* const* d_in, const int* in_sizes, int n_in,
                              void* d_out, int out_size) {
    const float* x  = (const float*)d_in[0];
    const float* h0 = (const float*)d_in[1];
    const float* c0 = (const float*)d_in[2];
    const float* Wx = (const float*)d_in[3];
    const float* Wh = (const float*)d_in[4];
    const float* bh = (const float*)d_in[5];
    float* out = (float*)d_out;

    permute_w<<<2048, 256>>>(Wx, Wh, bh);
    gemm_gx<<<dim3(G4 / 128, M_ROWS / 128), 256>>>(x);
    lstm_rec<<<128, 256>>>(h0, c0, out);
}

// round 4
// speedup vs baseline: 3.4101x; 3.4101x over previous
#include <cuda_runtime.h>
#include <cuda_bf16.h>
#include <cstdint>

#define S_LEN 512
#define BATCH 64
#define D_IN  512
#define H_DIM 1024
#define G4    4096
#define M_ROWS 32768
#define NBLK  128

// ---- recurrence SMEM layout (bytes) ----
// W: 16 chunks x (32 rows x 144B) hi then lo
#define RSM_WLO   73728
#define RSM_H     147456            // 3 bufs x (hi 9216 + lo 9216)
#define RSM_G     202752            // gates 64x32 f32
#define RSM_TOTAL 210944
// ---- gx GEMM SMEM: 3 bufs x 73728 (Ahi,Alo,Bhi,Blo @ 18432 each) ----
#define GSM_TOTAL 221184

// ---------------- device scratch ----------------
__device__ float g_bh_p[G4];
__device__ float g_gx[(size_t)M_ROWS * G4];
__device__ __nv_bfloat16 g_x_hi[(size_t)M_ROWS * D_IN];
__device__ __nv_bfloat16 g_x_lo[(size_t)M_ROWS * D_IN];
__device__ __nv_bfloat16 g_Wxb_hi[(size_t)G4 * D_IN];   // n-major, permuted
__device__ __nv_bfloat16 g_Wxb_lo[(size_t)G4 * D_IN];
__device__ __nv_bfloat16 g_Wr_hi[(size_t)NBLK * 36864]; // per-CTA padded chunk images
__device__ __nv_bfloat16 g_Wr_lo[(size_t)NBLK * 36864];
__device__ __nv_bfloat16 g_h_hi[2][BATCH * H_DIM];
__device__ __nv_bfloat16 g_h_lo[2][BATCH * H_DIM];
__device__ unsigned g_bar_count, g_bar_gen;

// ---------------- helpers ----------------
__device__ __forceinline__ uint32_t smem_u32(const void* p) {
    uint32_t a;
    asm("{ .reg .u64 t; cvta.to.shared.u64 t, %1; cvt.u32.u64 %0, t; }" : "=r"(a) : "l"(p));
    return a;
}
__device__ __forceinline__ void ldm4(uint32_t a, uint32_t& r0, uint32_t& r1, uint32_t& r2, uint32_t& r3) {
    asm volatile("ldmatrix.sync.aligned.m8n8.x4.shared.b16 {%0,%1,%2,%3}, [%4];"
                 : "=r"(r0), "=r"(r1), "=r"(r2), "=r"(r3) : "r"(a));
}
__device__ __forceinline__ void mma16816(float* c, uint32_t a0, uint32_t a1, uint32_t a2, uint32_t a3,
                                         uint32_t b0, uint32_t b1) {
    asm volatile("mma.sync.aligned.m16n8k16.row.col.f32.bf16.bf16.f32 "
                 "{%0,%1,%2,%3}, {%4,%5,%6,%7}, {%8,%9}, {%0,%1,%2,%3};"
                 : "+f"(c[0]), "+f"(c[1]), "+f"(c[2]), "+f"(c[3])
                 : "r"(a0), "r"(a1), "r"(a2), "r"(a3), "r"(b0), "r"(b1));
}
__device__ __forceinline__ void cp16(uint32_t dst, const void* src) {
    asm volatile("cp.async.cg.shared.global [%0], [%1], 16;" :: "r"(dst), "l"(src) : "memory");
}
__device__ __forceinline__ void cp_commit() { asm volatile("cp.async.commit_group;" ::: "memory"); }
__device__ __forceinline__ void cp_wait1()  { asm volatile("cp.async.wait_group 1;" ::: "memory"); }
__device__ __forceinline__ void cp_wait0()  { asm volatile("cp.async.wait_group 0;" ::: "memory"); }
__device__ __forceinline__ float sigm(float x) { return 1.0f / (1.0f + __expf(-x)); }

__device__ __forceinline__ void grid_sync(unsigned& bar) {
    __syncthreads();
    if (threadIdx.x == 0) {
        __threadfence();
        unsigned t = atomicAdd(&g_bar_count, 1u);
        bar += 1;
        if (t == gridDim.x - 1u) {
            atomicExch(&g_bar_count, 0u);
            __threadfence();
            atomicAdd(&g_bar_gen, 1u);
        } else {
            while ((int)(atomicAdd(&g_bar_gen, 0u) - bar) < 0) __nanosleep(64);
        }
    }
    __syncthreads();
}

// ---------------- prep: Wx -> n-major permuted bf16 hi/lo; bias ----------------
__global__ void prep_wxb(const float* __restrict__ Wx, const float* __restrict__ bh) {
    int idx = blockIdx.x * blockDim.x + threadIdx.x;      // 4096*512
    if (idx >= G4 * D_IN) return;
    int n = idx >> 9, k = idx & 511;
    float v = Wx[(size_t)k * G4 + (n & 3) * H_DIM + (n >> 2)];
    __nv_bfloat16 hi = __float2bfloat16(v);
    g_Wxb_hi[idx] = hi;
    g_Wxb_lo[idx] = __float2bfloat16(v - __bfloat162float(hi));
    if (k == 0) g_bh_p[n] = bh[(n & 3) * H_DIM + (n >> 2)];
}

// ---------------- prep: x -> bf16 hi/lo ----------------
__global__ void conv_x(const float* __restrict__ x) {
    size_t idx = (size_t)blockIdx.x * blockDim.x + threadIdx.x;
    if (idx >= (size_t)M_ROWS * D_IN) return;
    float v = x[idx];
    __nv_bfloat16 hi = __float2bfloat16(v);
    g_x_hi[idx] = hi;
    g_x_lo[idx] = __float2bfloat16(v - __bfloat162float(hi));
}

// ---------------- prep: per-CTA padded W chunk images ----------------
// image: 16 chunks x (32 n-rows x 72 elems [64 data + 8 pad])
__global__ void prep_wrec(const float* __restrict__ Wh) {
    size_t idx = (size_t)blockIdx.x * blockDim.x + threadIdx.x;
    if (idx >= (size_t)NBLK * 36864) return;
    int bid = (int)(idx / 36864);
    int e = (int)(idx % 36864);
    int c = e / 2304, rr = e % 2304;
    int n = rr / 72, k = rr % 72;
    __nv_bfloat16 hi = __float2bfloat16(0.f), lo = __float2bfloat16(0.f);
    if (k < 64) {
        int cn = bid * 32 + n;
        float v = Wh[(size_t)(c * 64 + k) * G4 + (cn & 3) * H_DIM + (cn >> 2)];
        hi = __float2bfloat16(v);
        lo = __float2bfloat16(v - __bfloat162float(hi));
    }
    g_Wr_hi[idx] = hi;
    g_Wr_lo[idx] = lo;
}

// ---------------- gx GEMM (mma.sync bf16 3-term): g_gx = x @ Wx_p ----------------
__global__ __launch_bounds__(512, 1) void gemm_gx() {
    extern __shared__ char smem[];
    const uint32_t sb = smem_u32(smem);
    const int tid = threadIdx.x, lane = tid & 31, w = tid >> 5;
    const int mB = blockIdx.y * 128, nB = blockIdx.x * 128;
    const int m0 = (w & 3) * 32, n0 = (w >> 2) * 32;

    float acc[2][4][4];
#pragma unroll
    for (int a = 0; a < 2; ++a)
#pragma unroll
        for (int b = 0; b < 4; ++b)
#pragma unroll
            for (int d = 0; d < 4; ++d) acc[a][b][d] = 0.f;

    uint32_t aoff[2], boff[2];
#pragma unroll
    for (int mt = 0; mt < 2; ++mt)
        aoff[mt] = (uint32_t)(m0 + mt * 16 + (lane & 15)) * 144u + (uint32_t)(lane >> 4) * 16u;
#pragma unroll
    for (int g = 0; g < 2; ++g)
        boff[g] = (uint32_t)(n0 + g * 16 + ((lane >> 4) << 3) + (lane & 7)) * 144u +
                  (uint32_t)((lane >> 3) & 1) * 16u;

#define GX_ISSUE(ch, buf) do {                                                     \
    _Pragma("unroll")                                                              \
    for (int q = 0; q < 8; ++q) {                                                  \
        int id = tid + q * 512;                                                    \
        int arr = id >> 10, rem = id & 1023, row = rem >> 3, seg = rem & 7;        \
        uint32_t dst = sb + (uint32_t)(buf) * 73728u + (uint32_t)arr * 18432u +    \
                       (uint32_t)row * 144u + (uint32_t)seg * 16u;                 \
        const __nv_bfloat16* src;                                                  \
        if (arr == 0)      src = g_x_hi + (size_t)(mB + row) * 512;                \
        else if (arr == 1) src = g_x_lo + (size_t)(mB + row) * 512;                \
        else if (arr == 2) src = g_Wxb_hi + (size_t)(nB + row) * 512;              \
        else               src = g_Wxb_lo + (size_t)(nB + row) * 512;              \
        cp16(dst, src + (ch) * 64 + seg * 8);                                      \
    }                                                                              \
    cp_commit();                                                                   \
} while (0)

    GX_ISSUE(0, 0);
    GX_ISSUE(1, 1);
    for (int c = 0; c < 8; ++c) {
        if (c < 7) cp_wait1(); else cp_wait0();
        __syncthreads();
        const uint32_t base = sb + (uint32_t)(c % 3) * 73728u;
#pragma unroll
        for (int kk = 0; kk < 4; ++kk) {
            const uint32_t o = kk * 32;
            uint32_t ah[2][4], al[2][4], bhv[2][4], blv[2][4];
#pragma unroll
            for (int mt = 0; mt < 2; ++mt) {
                ldm4(base + aoff[mt] + o, ah[mt][0], ah[mt][1], ah[mt][2], ah[mt][3]);
                ldm4(base + 18432u + aoff[mt] + o, al[mt][0], al[mt][1], al[mt][2], al[mt][3]);
            }
#pragma unroll
            for (int g = 0; g < 2; ++g) {
                ldm4(base + 36864u + boff[g] + o, bhv[g][0], bhv[g][1], bhv[g][2], bhv[g][3]);
                ldm4(base + 55296u + boff[g] + o, blv[g][0], blv[g][1], blv[g][2], blv[g][3]);
            }
#pragma unroll
            for (int mt = 0; mt < 2; ++mt)
#pragma unroll
                for (int g = 0; g < 2; ++g) {
                    mma16816(acc[mt][g * 2], ah[mt][0], ah[mt][1], ah[mt][2], ah[mt][3], bhv[g][0], bhv[g][1]);
                    mma16816(acc[mt][g * 2], al[mt][0], al[mt][1], al[mt][2], al[mt][3], bhv[g][0], bhv[g][1]);
                    mma16816(acc[mt][g * 2], ah[mt][0], ah[mt][1], ah[mt][2], ah[mt][3], blv[g][0], blv[g][1]);
                    mma16816(acc[mt][g * 2 + 1], ah[mt][0], ah[mt][1], ah[mt][2], ah[mt][3], bhv[g][2], bhv[g][3]);
                    mma16816(acc[mt][g * 2 + 1], al[mt][0], al[mt][1], al[mt][2], al[mt][3], bhv[g][2], bhv[g][3]);
                    mma16816(acc[mt][g * 2 + 1], ah[mt][0], ah[mt][1], ah[mt][2], ah[mt][3], blv[g][2], blv[g][3]);
                }
        }
        __syncthreads();
        if (c < 6) GX_ISSUE(c + 2, (c + 2) % 3);
    }
#undef GX_ISSUE
    // store
#pragma unroll
    for (int mt = 0; mt < 2; ++mt)
#pragma unroll
        for (int g = 0; g < 2; ++g)
#pragma unroll
            for (int hf = 0; hf < 2; ++hf) {
                int m = mB + m0 + mt * 16 + (lane >> 2);
                int n = nB + n0 + g * 16 + hf * 8 + (lane & 3) * 2;
                float* f = acc[mt][g * 2 + hf];
                *(float2*)&g_gx[(size_t)m * G4 + n] = make_float2(f[0], f[1]);
                *(float2*)&g_gx[(size_t)(m + 8) * G4 + n] = make_float2(f[2], f[3]);
            }
}

// ---------------- persistent mma.sync recurrence ----------------
__global__ __launch_bounds__(256, 1) void lstm_rec(const float* __restrict__ h0,
                                                   const float* __restrict__ c0,
                                                   float* __restrict__ out) {
    extern __shared__ char smem[];
    const uint32_t sb = smem_u32(smem);
    const int tid = threadIdx.x, lane = tid & 31, w = tid >> 5, bid = blockIdx.x;
    const int hcb = bid * 8;
    const int m0 = (w & 3) * 16, n0 = (w >> 2) * 16;

    // resident W slice
    {
        const int4* swh = (const int4*)(g_Wr_hi + (size_t)bid * 36864);
        const int4* swl = (const int4*)(g_Wr_lo + (size_t)bid * 36864);
        int4* dh = (int4*)smem;
        int4* dl = (int4*)(smem + RSM_WLO);
        for (int i = tid; i < 4608; i += 256) { dh[i] = swh[i]; dl[i] = swl[i]; }
    }
    // h0 -> bf16 hi/lo ping buffer 0 (disjoint slice per CTA)
    for (int i = tid; i < 512; i += 256) {
        int p = bid * 512 + i;
        float v = h0[p];
        __nv_bfloat16 hi = __float2bfloat16(v);
        g_h_hi[0][p] = hi;
        g_h_lo[0][p] = __float2bfloat16(v - __bfloat162float(hi));
    }
    // per-thread cell state + bias
    const int eb = tid >> 3, ehl = tid & 7;
    float c_r[2];
    c_r[0] = c0[eb * H_DIM + hcb + ehl];
    c_r[1] = c0[(eb + 32) * H_DIM + hcb + ehl];
    const float4 br = *(const float4*)&g_bh_p[bid * 32 + ehl * 4];

    const uint32_t a_off = (uint32_t)(m0 + (lane & 15)) * 144u + (uint32_t)(lane >> 4) * 16u;
    const uint32_t b_off = (uint32_t)(n0 + ((lane >> 4) << 3) + (lane & 7)) * 144u +
                           (uint32_t)((lane >> 3) & 1) * 16u;

    unsigned bar = 0;
    if (tid == 0) bar = atomicAdd(&g_bar_gen, 0u);
    grid_sync(bar);

    for (int t = 0; t < S_LEN; ++t) {
        const int nb = t & 1;
        // prefetch gx (raw, bias added below)
        float4 gv0 = *(const float4*)&g_gx[(size_t)(t * BATCH + eb) * G4 + bid * 32 + ehl * 4];
        float4 gv1 = *(const float4*)&g_gx[(size_t)(t * BATCH + eb + 32) * G4 + bid * 32 + ehl * 4];

        float acc0[4] = {0.f, 0.f, 0.f, 0.f};
        float acc1[4] = {0.f, 0.f, 0.f, 0.f};

#define H_ISSUE(ch, buf) do {                                                      \
    _Pragma("unroll")                                                              \
    for (int q = 0; q < 4; ++q) {                                                  \
        int id = tid + q * 256;                                                    \
        int img = id >> 9, rem = id & 511, row = rem >> 3, seg = rem & 7;          \
        uint32_t dst = sb + RSM_H + (uint32_t)(buf) * 18432u +                     \
                       (uint32_t)img * 9216u + (uint32_t)row * 144u +              \
                       (uint32_t)seg * 16u;                                        \
        const __nv_bfloat16* src = (img ? g_h_lo[nb] : g_h_hi[nb]) +               \
                                   row * H_DIM + (ch) * 64 + seg * 8;              \
        cp16(dst, src);                                                            \
    }                                                                              \
    cp_commit();                                                                   \
} while (0)

        H_ISSUE(0, 0);
        H_ISSUE(1, 1);
        for (int c = 0; c < 16; ++c) {
            if (c < 15) cp_wait1(); else cp_wait0();
            __syncthreads();
            const uint32_t ah = sb + RSM_H + (uint32_t)(c % 3) * 18432u + a_off;
            const uint32_t al = ah + 9216u;
            const uint32_t bh = sb + (uint32_t)c * 4608u + b_off;
            const uint32_t bl = bh + RSM_WLO;
#pragma unroll
            for (int kk = 0; kk < 4; ++kk) {
                const uint32_t o = kk * 32;
                uint32_t A0, A1, A2, A3, L0, L1, L2, L3;
                uint32_t B0, B1, B2, B3, C0, C1, C2, C3;
                ldm4(ah + o, A0, A1, A2, A3);
                ldm4(al + o, L0, L1, L2, L3);
                ldm4(bh + o, B0, B1, B2, B3);
                ldm4(bl + o, C0, C1, C2, C3);
                mma16816(acc0, A0, A1, A2, A3, B0, B1);
                mma16816(acc0, L0, L1, L2, L3, B0, B1);
                mma16816(acc0, A0, A1, A2, A3, C0, C1);
                mma16816(acc1, A0, A1, A2, A3, B2, B3);
                mma16816(acc1, L0, L1, L2, L3, B2, B3);
                mma16816(acc1, A0, A1, A2, A3, C2, C3);
            }
            if (c < 14) H_ISSUE(c + 2, (c + 2) % 3);
        }
#undef H_ISSUE

        // stage gates
        {
            float* G = (float*)(smem + RSM_G);
            int r0 = m0 + (lane >> 2), cb0 = n0 + (lane & 3) * 2;
            *(float2*)&G[r0 * 32 + cb0] = make_float2(acc0[0], acc0[1]);
            *(float2*)&G[(r0 + 8) * 32 + cb0] = make_float2(acc0[2], acc0[3]);
            *(float2*)&G[r0 * 32 + cb0 + 8] = make_float2(acc1[0], acc1[1]);
            *(float2*)&G[(r0 + 8) * 32 + cb0 + 8] = make_float2(acc1[2], acc1[3]);
        }
        __syncthreads();

        // elementwise LSTM for (eb, ehl) and (eb+32, ehl)
        const int nb2 = nb ^ 1;
        const float* G = (const float*)(smem + RSM_G);
#pragma unroll
        for (int q = 0; q < 2; ++q) {
            int b = eb + q * 32;
            float4 gr = *(const float4*)&G[b * 32 + ehl * 4];
            float4 gx = q ? gv1 : gv0;
            float gi = gr.x + gx.x + br.x;
            float gf = gr.y + gx.y + br.y;
            float gj = gr.z + gx.z + br.z;
            float go = gr.w + gx.w + br.w;
            float cn = c_r[q] * sigm(gf + 1.0f) + sigm(gi) * tanhf(gj);
            c_r[q] = cn;
            float hn = tanhf(cn) * sigm(go);
            __nv_bfloat16 hh = __float2bfloat16(hn);
            g_h_hi[nb2][b * H_DIM + hcb + ehl] = hh;
            g_h_lo[nb2][b * H_DIM + hcb + ehl] = __float2bfloat16(hn - __bfloat162float(hh));
            if (t == S_LEN - 1) {
                out[b * H_DIM + hcb + ehl] = hn;
                out[BATCH * H_DIM + b * H_DIM + hcb + ehl] = cn;
            }
        }
        grid_sync(bar);
    }
}

// ---------------- host launch ----------------
extern "C" void kernel_launch(void* const* d_in, const int* in_sizes, int n_in,
                              void* d_out, int out_size) {
    const float* x  = (const float*)d_in[0];
    const float* h0 = (const float*)d_in[1];
    const float* c0 = (const float*)d_in[2];
    const float* Wx = (const float*)d_in[3];
    const float* Wh = (const float*)d_in[4];
    const float* bh = (const float*)d_in[5];
    float* out = (float*)d_out;

    prep_wxb<<<(G4 * D_IN + 255) / 256, 256>>>(Wx, bh);
    conv_x<<<(M_ROWS * D_IN + 511) / 512, 512>>>(x);
    prep_wrec<<<(NBLK * 36864 + 255) / 256, 256>>>(Wh);
    cudaFuncSetAttribute(gemm_gx, cudaFuncAttributeMaxDynamicSharedMemorySize, GSM_TOTAL);
    gemm_gx<<<dim3(G4 / 128, M_ROWS / 128), 512, GSM_TOTAL>>>();
    cudaFuncSetAttribute(lstm_rec, cudaFuncAttributeMaxDynamicSharedMemorySize, RSM_TOTAL);
    lstm_rec<<<NBLK, 256, RSM_TOTAL>>>(h0, c0, out);
}